// round 15
// baseline (speedup 1.0000x reference)
#include <cuda_runtime.h>
#include <cuda_fp16.h>
#include <cstdint>
#include <cstddef>

#define D_   2048
#define NC_  2
#define DS_  16
#define BL_  1024           // B*L = 2*512
#define N1_  4096           // NC*D

// ---------------- scratch (static device globals; no allocation) -----------
__device__ __half g_Wh1[(size_t)N1_ * D_];   // fp16 W_in   (16 MB)
__device__ __half g_Wh2[(size_t)D_ * N1_];   // fp16 W_out  (16 MB)
__device__ __half g_xh [(size_t)BL_ * D_];   // fp16 x      (2 MB)
__device__ __half g_xih[(size_t)BL_ * N1_];  // fp16 xi     (8 MB)
__device__ __half g_yh [(size_t)BL_ * N1_];  // fp16 y = xi*gate (8 MB)
__device__ float  g_o  [(size_t)BL_ * D_];   // out pre-norm (8 MB)
__device__ float  g_gate[N1_];

// ---------------- helpers ---------------------------------------------------
__device__ __forceinline__ void cpa16(const void* s, const void* g) {
    unsigned sa = (unsigned)__cvta_generic_to_shared(s);
    asm volatile("cp.async.cg.shared.global [%0], [%1], 16;\n" :: "r"(sa), "l"(g));
}
__device__ __forceinline__ void ldsm4(unsigned& r0, unsigned& r1,
                                      unsigned& r2, unsigned& r3, uint32_t a) {
    asm volatile("ldmatrix.sync.aligned.m8n8.x4.shared.b16 {%0,%1,%2,%3}, [%4];"
                 : "=r"(r0), "=r"(r1), "=r"(r2), "=r"(r3) : "r"(a));
}
__device__ __forceinline__ void stcs(float4* p, float4 v) {
    asm volatile("st.global.cs.v4.f32 [%0], {%1,%2,%3,%4};"
                 :: "l"(p), "f"(v.x), "f"(v.y), "f"(v.z), "f"(v.w) : "memory");
}

// ---------------- fp32 -> fp16 convert --------------------------------------
__global__ void to_half(const float4* __restrict__ s, __half2* __restrict__ d, int n4) {
    int i = blockIdx.x * blockDim.x + threadIdx.x;
    if (i >= n4) return;
    float4 v = s[i];
    d[2 * i]     = __floats2half2_rn(v.x, v.y);
    d[2 * i + 1] = __floats2half2_rn(v.z, v.w);
}
__global__ void to_half2(const float4* __restrict__ a, __half2* __restrict__ da, int na,
                         const float4* __restrict__ b, __half2* __restrict__ db, int nb) {
    int i = blockIdx.x * blockDim.x + threadIdx.x;
    const float4* s; __half2* d; int idx;
    if (i < na)           { s = a; d = da; idx = i; }
    else if (i < na + nb) { s = b; d = db; idx = i - na; }
    else return;
    float4 v = s[idx];
    d[2 * idx]     = __floats2half2_rn(v.x, v.y);
    d[2 * idx + 1] = __floats2half2_rn(v.z, v.w);
}

// ---------------- gate: g[n] = sum_ds(Cr*Br - Ci*Bi), 4 lanes per n ---------
__global__ void compute_gate(const float4* __restrict__ Br, const float4* __restrict__ Bi,
                             const float4* __restrict__ Cr, const float4* __restrict__ Ci) {
    int t = blockIdx.x * blockDim.x + threadIdx.x;   // 0 .. 4*N1_-1
    int n = t >> 2, j = t & 3;
    if (n >= N1_) return;
    float4 cr = Cr[n * 4 + j], br = Br[n * 4 + j];
    float4 ci = Ci[n * 4 + j], bi = Bi[n * 4 + j];
    float s = 0.f;
    s = fmaf(cr.x, br.x, s); s = fmaf(-ci.x, bi.x, s);
    s = fmaf(cr.y, br.y, s); s = fmaf(-ci.y, bi.y, s);
    s = fmaf(cr.z, br.z, s); s = fmaf(-ci.z, bi.z, s);
    s = fmaf(cr.w, br.w, s); s = fmaf(-ci.w, bi.w, s);
    s += __shfl_down_sync(0xFFFFFFFFu, s, 2);
    s += __shfl_down_sync(0xFFFFFFFFu, s, 1);
    if (j == 0) g_gate[n] = s;
}

// ---------------- state emission: nr = Br*xi, ni = Bi*xi --------------------
// Tiny CTAs (64 threads) so this co-resides with GEMM2 on every SM:
// 2x(64thr,~2.6K regs) + 2x GEMM2 CTAs (55K regs) fits the 64K RF.
__global__ __launch_bounds__(64) void ew_state(
    const __half* __restrict__ xi,
    const float4* __restrict__ brp, const float4* __restrict__ bip,
    float4* __restrict__ nr4, float4* __restrict__ ni4) {
    const int stride = gridDim.x * blockDim.x;
    for (int t = blockIdx.x * blockDim.x + threadIdx.x;
         t < BL_ * N1_ * 4; t += stride) {
        int row = t >> 14;
        int idx = t & 16383;
        int col = idx >> 2;
        int jj  = idx & 3;
        float v = __half2float(__ldg(&xi[(size_t)row * N1_ + col]));
        float4 br = __ldg(&brp[col * 4 + jj]);
        stcs(&nr4[t], make_float4(br.x * v, br.y * v, br.z * v, br.w * v));
        float4 bi = __ldg(&bip[col * 4 + jj]);
        stcs(&ni4[t], make_float4(bi.x * v, bi.y * v, bi.z * v, bi.w * v));
    }
}

// ---------------- TN GEMM: C[M,N] = A[M,K] * B[N,K]^T -----------------------
// CTA 128x128, BK=32, 4 warps (2x2, each 64x64 output), 4-stage cp.async,
// 128 threads, 2 CTAs/SM. WRITE_Y: also emit y = xi*gate (GEMM1 path).
template<bool HALF_OUT, bool WRITE_Y>
__global__ __launch_bounds__(128, 2) void gemm_tn(
    const __half* __restrict__ A, const __half* __restrict__ B,
    float* __restrict__ Cf, __half* __restrict__ Ch, __half* __restrict__ Yh,
    int ldc, int K)
{
    constexpr int S   = 4;
    constexpr int RS  = 40;                   // halves per smem row (32 + 8 pad)
    constexpr int MI  = 4;                    // 4 m-tiles of 16 (64 rows / warp)
    constexpr int JN  = 8;                    // 8 n-tiles of 8 (64 cols / warp)
    constexpr int AST = 128 * RS;             // halves per A stage
    constexpr int BST = 128 * RS;

    extern __shared__ __half sm[];

    const int tid  = threadIdx.x;
    const int lane = tid & 31;
    const int wid  = tid >> 5;                // 0..3
    const int wm   = (wid & 1) * 64;          // warp m-offset
    const int wn   = (wid >> 1) * 64;         // warp n-offset
    const int gid  = lane >> 2;
    const int q    = lane & 3;
    const int row0 = blockIdx.y * 128;
    const int col0 = blockIdx.x * 128;

    const int lr = tid >> 2;                  // loader row (0..31)
    const int ls = (tid & 3) * 8;             // loader half-offset (16B)

    const int lr8 = lane & 7;
    const int lg  = lane >> 3;                // 0..3
    const uint32_t sm_u = (uint32_t)__cvta_generic_to_shared(sm);
    const uint32_t A_u  = sm_u;
    const uint32_t B_u  = sm_u + S * AST * 2;
    const uint32_t a_off = (uint32_t)(((wm + (lg & 1) * 8 + lr8) * RS + (lg >> 1) * 8) * 2);
    const uint32_t b_off = (uint32_t)(((wn + (lg >> 1) * 8 + lr8) * RS + (lg & 1) * 8) * 2);

    __half* As = sm;
    __half* Bs = sm + S * AST;

    float cr[MI][JN][4];
    #pragma unroll
    for (int i = 0; i < MI; i++)
        #pragma unroll
        for (int j = 0; j < JN; j++)
            #pragma unroll
            for (int t = 0; t < 4; t++) cr[i][j][t] = 0.f;

    auto issue = [&](int st, int k0) {
        #pragma unroll
        for (int i = 0; i < 4; i++) {                  // A: 128 rows, 4 groups
            int r = lr + i * 32;
            cpa16(&As[st * AST + r * RS + ls], A + (size_t)(row0 + r) * K + k0 + ls);
        }
        #pragma unroll
        for (int i = 0; i < 4; i++) {                  // B: 128 rows, 4 groups
            int r = lr + i * 32;
            cpa16(&Bs[st * BST + r * RS + ls], B + (size_t)(col0 + r) * K + k0 + ls);
        }
        asm volatile("cp.async.commit_group;\n");
    };

    auto compute = [&](int st) {
        const uint32_t ab = A_u + st * (AST * 2) + a_off;
        const uint32_t bb = B_u + st * (BST * 2) + b_off;
        #pragma unroll
        for (int ks = 0; ks < 2; ks++) {
            const uint32_t kbb = ks * 32;              // 16 halves = 32 bytes
            unsigned a[MI][4], bp[4][4];
            #pragma unroll
            for (int i = 0; i < MI; i++)
                ldsm4(a[i][0], a[i][1], a[i][2], a[i][3],
                      ab + i * (16 * RS * 2) + kbb);
            #pragma unroll
            for (int jp = 0; jp < 4; jp++)
                ldsm4(bp[jp][0], bp[jp][1], bp[jp][2], bp[jp][3],
                      bb + jp * (16 * RS * 2) + kbb);
            #pragma unroll
            for (int i = 0; i < MI; i++)
                #pragma unroll
                for (int j = 0; j < JN; j++) {
                    const unsigned b0 = bp[j >> 1][(j & 1) * 2];
                    const unsigned b1 = bp[j >> 1][(j & 1) * 2 + 1];
                    asm volatile(
                        "mma.sync.aligned.m16n8k16.row.col.f32.f16.f16.f32 "
                        "{%0,%1,%2,%3}, {%4,%5,%6,%7}, {%8,%9}, {%0,%1,%2,%3};\n"
                        : "+f"(cr[i][j][0]), "+f"(cr[i][j][1]),
                          "+f"(cr[i][j][2]), "+f"(cr[i][j][3])
                        : "r"(a[i][0]), "r"(a[i][1]), "r"(a[i][2]), "r"(a[i][3]),
                          "r"(b0), "r"(b1));
                }
        }
    };

    const int nt = K / 32;
    #pragma unroll
    for (int s = 0; s < S - 1; s++) issue(s, s * 32);
    asm volatile("cp.async.wait_group %0;\n" :: "n"(S - 2));
    __syncthreads();

    for (int kt = 0; kt < nt; kt++) {
        int nk = kt + S - 1;
        if (nk < nt) issue(nk % S, nk * 32);
        else asm volatile("cp.async.commit_group;\n");
        compute(kt % S);
        asm volatile("cp.async.wait_group %0;\n" :: "n"(S - 2));
        __syncthreads();
    }

    // ---------------- epilogue ----------------
    #pragma unroll
    for (int i = 0; i < MI; i++)
        #pragma unroll
        for (int j = 0; j < JN; j++) {
            int r  = row0 + wm + i * 16 + gid;
            int cn = col0 + wn + j * 8 + q * 2;
            if (HALF_OUT) {
                *reinterpret_cast<__half2*>(Ch + (size_t)r * ldc + cn) =
                    __floats2half2_rn(cr[i][j][0], cr[i][j][1]);
                *reinterpret_cast<__half2*>(Ch + (size_t)(r + 8) * ldc + cn) =
                    __floats2half2_rn(cr[i][j][2], cr[i][j][3]);
                if (WRITE_Y) {
                    float g0 = __ldg(&g_gate[cn]), g1 = __ldg(&g_gate[cn + 1]);
                    *reinterpret_cast<__half2*>(Yh + (size_t)r * ldc + cn) =
                        __floats2half2_rn(cr[i][j][0] * g0, cr[i][j][1] * g1);
                    *reinterpret_cast<__half2*>(Yh + (size_t)(r + 8) * ldc + cn) =
                        __floats2half2_rn(cr[i][j][2] * g0, cr[i][j][3] * g1);
                }
            } else {
                *reinterpret_cast<float2*>(Cf + (size_t)r * ldc + cn) =
                    make_float2(cr[i][j][0], cr[i][j][1]);
                *reinterpret_cast<float2*>(Cf + (size_t)(r + 8) * ldc + cn) =
                    make_float2(cr[i][j][2], cr[i][j][3]);
            }
        }
}

// ---------------- rmsnorm + residual ----------------------------------------
__global__ __launch_bounds__(256) void rms_kernel(const float* __restrict__ x,
                                                  const float* __restrict__ w,
                                                  float* __restrict__ out)
{
    const int row = blockIdx.x;
    const float* o = g_o + (size_t)row * D_;
    float s = 0.f;
    for (int d = threadIdx.x; d < D_; d += 256) {
        float v = o[d];
        s = fmaf(v, v, s);
    }
    __shared__ float red[8];
    #pragma unroll
    for (int off = 16; off; off >>= 1) s += __shfl_xor_sync(0xFFFFFFFFu, s, off);
    if ((threadIdx.x & 31) == 0) red[threadIdx.x >> 5] = s;
    __syncthreads();
    if (threadIdx.x < 8) {
        float t = red[threadIdx.x];
        #pragma unroll
        for (int off = 4; off; off >>= 1) t += __shfl_xor_sync(0xFFu, t, off);
        if (threadIdx.x == 0) red[0] = t;
    }
    __syncthreads();
    const float scale = rsqrtf(red[0] * (1.0f / D_) + 1.1920928955078125e-7f);
    for (int d = threadIdx.x; d < D_; d += 256) {
        out[(size_t)row * D_ + d] =
            x[(size_t)row * D_ + d] + o[d] * scale * w[d];
    }
}

// ---------------- launch -----------------------------------------------------
extern "C" void kernel_launch(void* const* d_in, const int* in_sizes, int n_in,
                              void* d_out, int out_size)
{
    const float* x     = (const float*)d_in[0];
    const float* W_in  = (const float*)d_in[1];
    const float* W_out = (const float*)d_in[2];
    // d_in[3] = A_theta: dead (initial state is zero)
    const float* Br    = (const float*)d_in[4];
    const float* Bi    = (const float*)d_in[5];
    const float* Cr    = (const float*)d_in[6];
    const float* Ci    = (const float*)d_in[7];
    const float* nw    = (const float*)d_in[8];

    float* out0 = (float*)d_out;
    const long long FULL =
        (long long)BL_ * D_ + 2LL * BL_ * N1_ * DS_;   // 136,314,880
    const int write_state = ((long long)out_size >= FULL) ? 1 : 0;
    float* nr = out0 + (size_t)BL_ * D_;
    float* ni = nr + (size_t)BL_ * N1_ * DS_;

    void *w1_p = nullptr, *w2_p = nullptr, *xh_p = nullptr, *xih_p = nullptr,
         *yh_p = nullptr, *o_p = nullptr;
    cudaGetSymbolAddress(&w1_p,  g_Wh1);
    cudaGetSymbolAddress(&w2_p,  g_Wh2);
    cudaGetSymbolAddress(&xh_p,  g_xh);
    cudaGetSymbolAddress(&xih_p, g_xih);
    cudaGetSymbolAddress(&yh_p,  g_yh);
    cudaGetSymbolAddress(&o_p,   g_o);

    const int SMEM = 4 * (128 + 128) * 40 * 2;   // 81,920 B
    cudaFuncSetAttribute((const void*)gemm_tn<true,  true >,
                         cudaFuncAttributeMaxDynamicSharedMemorySize, SMEM);
    cudaFuncSetAttribute((const void*)gemm_tn<false, false>,
                         cudaFuncAttributeMaxDynamicSharedMemorySize, SMEM);

    static cudaStream_t side = nullptr;
    static cudaEvent_t evF = nullptr, evW2 = nullptr, evXI = nullptr, evST = nullptr;
    if (!side) {
        if (cudaStreamCreateWithFlags(&side, cudaStreamNonBlocking) != cudaSuccess)
            side = nullptr;
        if (side) {
            cudaEventCreateWithFlags(&evF,  cudaEventDisableTiming);
            cudaEventCreateWithFlags(&evW2, cudaEventDisableTiming);
            cudaEventCreateWithFlags(&evXI, cudaEventDisableTiming);
            cudaEventCreateWithFlags(&evST, cudaEventDisableTiming);
        }
    }
    const bool fork = (side != nullptr);

    const int na = N1_ * D_ / 4;   // W_in float4 count
    const int nb = D_ * N1_ / 4;   // W_out float4 count
    const int nc = BL_ * D_ / 4;   // x float4 count

    const dim3 G1(N1_ / 128, BL_ / 128);   // 32 x 8 = 256 CTAs
    const dim3 G2(D_  / 128, BL_ / 128);   // 16 x 8 = 128 CTAs

    if (fork) {
        cudaEventRecord(evF, 0);
        cudaStreamWaitEvent(side, evF, 0);

        // side: convert W_out (only needed by GEMM2)
        to_half<<<(nb + 255) / 256, 256, 0, side>>>(
            (const float4*)W_out, (__half2*)w2_p, nb);
        cudaEventRecord(evW2, side);

        // main: convert W_in + x, gate, GEMM1 (writes xi AND y)
        to_half2<<<(na + nc + 255) / 256, 256>>>(
            (const float4*)W_in, (__half2*)w1_p, na,
            (const float4*)x,    (__half2*)xh_p, nc);
        compute_gate<<<(4 * N1_) / 256, 256>>>(
            (const float4*)Br, (const float4*)Bi,
            (const float4*)Cr, (const float4*)Ci);
        gemm_tn<true, true><<<G1, 128, SMEM>>>(
            (const __half*)xh_p, (const __half*)w1_p,
            nullptr, (__half*)xih_p, (__half*)yh_p, N1_, D_);

        // side: nr/ni emission (tiny CTAs -> co-resides with GEMM2)
        cudaEventRecord(evXI, 0);
        cudaStreamWaitEvent(side, evXI, 0);
        if (write_state) {
            ew_state<<<296, 64, 0, side>>>(
                (const __half*)xih_p,
                (const float4*)Br, (const float4*)Bi,
                (float4*)nr, (float4*)ni);
        }
        cudaEventRecord(evST, side);

        // main: GEMM2, rms
        cudaStreamWaitEvent(0, evW2, 0);
        gemm_tn<false, false><<<G2, 128, SMEM>>>(
            (const __half*)yh_p, (const __half*)w2_p,
            (float*)o_p, nullptr, nullptr, D_, N1_);
        rms_kernel<<<BL_, 256>>>(x, nw, out0);

        cudaStreamWaitEvent(0, evST, 0);
    } else {
        to_half<<<(nb + 255) / 256, 256>>>((const float4*)W_out, (__half2*)w2_p, nb);
        to_half2<<<(na + nc + 255) / 256, 256>>>(
            (const float4*)W_in, (__half2*)w1_p, na,
            (const float4*)x,    (__half2*)xh_p, nc);
        compute_gate<<<(4 * N1_) / 256, 256>>>(
            (const float4*)Br, (const float4*)Bi,
            (const float4*)Cr, (const float4*)Ci);
        gemm_tn<true, true><<<G1, 128, SMEM>>>(
            (const __half*)xh_p, (const __half*)w1_p,
            nullptr, (__half*)xih_p, (__half*)yh_p, N1_, D_);
        gemm_tn<false, false><<<G2, 128, SMEM>>>(
            (const __half*)yh_p, (const __half*)w2_p,
            (float*)o_p, nullptr, nullptr, D_, N1_);
        if (write_state) {
            ew_state<<<296, 64>>>(
                (const __half*)xih_p,
                (const float4*)Br, (const float4*)Bi,
                (float4*)nr, (float4*)ni);
        }
        rms_kernel<<<BL_, 256>>>(x, nw, out0);
    }
}

// round 16
// speedup vs baseline: 2.2737x; 2.2737x over previous
#include <cuda_runtime.h>
#include <cuda_fp16.h>
#include <cstdint>
#include <cstddef>

#define D_   2048
#define NC_  2
#define DS_  16
#define BL_  1024           // B*L = 2*512
#define N1_  4096           // NC*D

// ---------------- scratch (static device globals; no allocation) -----------
__device__ __half g_Wh1[(size_t)N1_ * D_];   // fp16 W_in   (16 MB)
__device__ __half g_Wh2[(size_t)D_ * N1_];   // fp16 W_out  (16 MB)
__device__ __half g_xh [(size_t)BL_ * D_];   // fp16 x      (2 MB)
__device__ __half g_xih[(size_t)BL_ * N1_];  // fp16 xi     (8 MB)
__device__ __half g_yh [(size_t)BL_ * N1_];  // fp16 y = xi*gate (8 MB)
__device__ float  g_o  [(size_t)BL_ * D_];   // out pre-norm (8 MB)
__device__ float  g_gate[N1_];

// ---------------- helpers ---------------------------------------------------
__device__ __forceinline__ void cpa16(const void* s, const void* g) {
    unsigned sa = (unsigned)__cvta_generic_to_shared(s);
    asm volatile("cp.async.cg.shared.global [%0], [%1], 16;\n" :: "r"(sa), "l"(g));
}
__device__ __forceinline__ void ldsm4(unsigned& r0, unsigned& r1,
                                      unsigned& r2, unsigned& r3, uint32_t a) {
    asm volatile("ldmatrix.sync.aligned.m8n8.x4.shared.b16 {%0,%1,%2,%3}, [%4];"
                 : "=r"(r0), "=r"(r1), "=r"(r2), "=r"(r3) : "r"(a));
}
__device__ __forceinline__ void stcs(float4* p, float4 v) {
    asm volatile("st.global.cs.v4.f32 [%0], {%1,%2,%3,%4};"
                 :: "l"(p), "f"(v.x), "f"(v.y), "f"(v.z), "f"(v.w) : "memory");
}

// ---------------- fp32 -> fp16 convert --------------------------------------
__global__ void to_half(const float4* __restrict__ s, __half2* __restrict__ d, int n4) {
    int i = blockIdx.x * blockDim.x + threadIdx.x;
    if (i >= n4) return;
    float4 v = s[i];
    d[2 * i]     = __floats2half2_rn(v.x, v.y);
    d[2 * i + 1] = __floats2half2_rn(v.z, v.w);
}
__global__ void to_half2(const float4* __restrict__ a, __half2* __restrict__ da, int na,
                         const float4* __restrict__ b, __half2* __restrict__ db, int nb) {
    int i = blockIdx.x * blockDim.x + threadIdx.x;
    const float4* s; __half2* d; int idx;
    if (i < na)           { s = a; d = da; idx = i; }
    else if (i < na + nb) { s = b; d = db; idx = i - na; }
    else return;
    float4 v = s[idx];
    d[2 * idx]     = __floats2half2_rn(v.x, v.y);
    d[2 * idx + 1] = __floats2half2_rn(v.z, v.w);
}

// ---------------- gate: g[n] = sum_ds(Cr*Br - Ci*Bi), 4 lanes per n ---------
__global__ void compute_gate(const float4* __restrict__ Br, const float4* __restrict__ Bi,
                             const float4* __restrict__ Cr, const float4* __restrict__ Ci) {
    int t = blockIdx.x * blockDim.x + threadIdx.x;   // 0 .. 4*N1_-1
    int n = t >> 2, j = t & 3;
    if (n >= N1_) return;
    float4 cr = Cr[n * 4 + j], br = Br[n * 4 + j];
    float4 ci = Ci[n * 4 + j], bi = Bi[n * 4 + j];
    float s = 0.f;
    s = fmaf(cr.x, br.x, s); s = fmaf(-ci.x, bi.x, s);
    s = fmaf(cr.y, br.y, s); s = fmaf(-ci.y, bi.y, s);
    s = fmaf(cr.z, br.z, s); s = fmaf(-ci.z, bi.z, s);
    s = fmaf(cr.w, br.w, s); s = fmaf(-ci.w, bi.w, s);
    s += __shfl_down_sync(0xFFFFFFFFu, s, 2);
    s += __shfl_down_sync(0xFFFFFFFFu, s, 1);
    if (j == 0) g_gate[n] = s;
}

// ---------------- state emission: nr = Br*xi, ni = Bi*xi --------------------
// 512 CTAs x 256 threads (the measured-best shape; HBM-write-roof bound).
__global__ void ew_state(const __half* __restrict__ xi,
                         const float4* __restrict__ brp, const float4* __restrict__ bip,
                         float4* __restrict__ nr4, float4* __restrict__ ni4) {
    const int stride = gridDim.x * blockDim.x;
    for (int t = blockIdx.x * blockDim.x + threadIdx.x;
         t < BL_ * N1_ * 4; t += stride) {
        int row = t >> 14;
        int idx = t & 16383;
        int col = idx >> 2;
        int jj  = idx & 3;
        float v = __half2float(__ldg(&xi[(size_t)row * N1_ + col]));
        float4 br = __ldg(&brp[col * 4 + jj]);
        stcs(&nr4[t], make_float4(br.x * v, br.y * v, br.z * v, br.w * v));
        float4 bi = __ldg(&bip[col * 4 + jj]);
        stcs(&ni4[t], make_float4(bi.x * v, bi.y * v, bi.z * v, bi.w * v));
    }
}

// ---------------- TN GEMM: C[M,N] = A[M,K] * B[N,K]^T -----------------------
// CTA 128x128, BK=64, 4 warps (2x2, each 64x64 output), 3-stage cp.async,
// 128 threads, 2 CTAs/SM. WRITE_Y: also emit y = xi*gate (GEMM1 path).
template<bool HALF_OUT, bool WRITE_Y>
__global__ __launch_bounds__(128, 2) void gemm_tn(
    const __half* __restrict__ A, const __half* __restrict__ B,
    float* __restrict__ Cf, __half* __restrict__ Ch, __half* __restrict__ Yh,
    int ldc, int K)
{
    constexpr int S   = 3;
    constexpr int RS  = 72;                   // halves per smem row (64 + 8 pad)
    constexpr int MI  = 4;                    // 4 m-tiles of 16 (64 rows / warp)
    constexpr int JN  = 8;                    // 8 n-tiles of 8 (64 cols / warp)
    constexpr int AST = 128 * RS;             // halves per A stage
    constexpr int BST = 128 * RS;

    extern __shared__ __half sm[];

    const int tid  = threadIdx.x;
    const int lane = tid & 31;
    const int wid  = tid >> 5;                // 0..3
    const int wm   = (wid & 1) * 64;          // warp m-offset
    const int wn   = (wid >> 1) * 64;         // warp n-offset
    const int gid  = lane >> 2;
    const int q    = lane & 3;
    const int row0 = blockIdx.y * 128;
    const int col0 = blockIdx.x * 128;

    const int lr = tid >> 3;                  // loader row (0..15)
    const int ls = (tid & 7) * 8;             // loader half-offset (16B)

    const int lr8 = lane & 7;
    const int lg  = lane >> 3;                // 0..3
    const uint32_t sm_u = (uint32_t)__cvta_generic_to_shared(sm);
    const uint32_t A_u  = sm_u;
    const uint32_t B_u  = sm_u + S * AST * 2;
    const uint32_t a_off = (uint32_t)(((wm + (lg & 1) * 8 + lr8) * RS + (lg >> 1) * 8) * 2);
    const uint32_t b_off = (uint32_t)(((wn + (lg >> 1) * 8 + lr8) * RS + (lg & 1) * 8) * 2);

    __half* As = sm;
    __half* Bs = sm + S * AST;

    float cr[MI][JN][4];
    #pragma unroll
    for (int i = 0; i < MI; i++)
        #pragma unroll
        for (int j = 0; j < JN; j++)
            #pragma unroll
            for (int t = 0; t < 4; t++) cr[i][j][t] = 0.f;

    auto issue = [&](int st, int k0) {
        #pragma unroll
        for (int i = 0; i < 8; i++) {                  // A: 128 rows, 8 groups
            int r = lr + i * 16;
            cpa16(&As[st * AST + r * RS + ls], A + (size_t)(row0 + r) * K + k0 + ls);
        }
        #pragma unroll
        for (int i = 0; i < 8; i++) {                  // B: 128 rows, 8 groups
            int r = lr + i * 16;
            cpa16(&Bs[st * BST + r * RS + ls], B + (size_t)(col0 + r) * K + k0 + ls);
        }
        asm volatile("cp.async.commit_group;\n");
    };

    auto compute = [&](int st) {
        const uint32_t ab = A_u + st * (AST * 2) + a_off;
        const uint32_t bb = B_u + st * (BST * 2) + b_off;
        #pragma unroll
        for (int ks = 0; ks < 4; ks++) {               // 4 k-halves of 16
            const uint32_t kbb = ks * 32;              // 16 halves = 32 bytes
            unsigned a[MI][4], bp[4][4];
            #pragma unroll
            for (int i = 0; i < MI; i++)
                ldsm4(a[i][0], a[i][1], a[i][2], a[i][3],
                      ab + i * (16 * RS * 2) + kbb);
            #pragma unroll
            for (int jp = 0; jp < 4; jp++)
                ldsm4(bp[jp][0], bp[jp][1], bp[jp][2], bp[jp][3],
                      bb + jp * (16 * RS * 2) + kbb);
            #pragma unroll
            for (int i = 0; i < MI; i++)
                #pragma unroll
                for (int j = 0; j < JN; j++) {
                    const unsigned b0 = bp[j >> 1][(j & 1) * 2];
                    const unsigned b1 = bp[j >> 1][(j & 1) * 2 + 1];
                    asm volatile(
                        "mma.sync.aligned.m16n8k16.row.col.f32.f16.f16.f32 "
                        "{%0,%1,%2,%3}, {%4,%5,%6,%7}, {%8,%9}, {%0,%1,%2,%3};\n"
                        : "+f"(cr[i][j][0]), "+f"(cr[i][j][1]),
                          "+f"(cr[i][j][2]), "+f"(cr[i][j][3])
                        : "r"(a[i][0]), "r"(a[i][1]), "r"(a[i][2]), "r"(a[i][3]),
                          "r"(b0), "r"(b1));
                }
        }
    };

    const int nt = K / 64;
    #pragma unroll
    for (int s = 0; s < S - 1; s++) issue(s, s * 64);
    asm volatile("cp.async.wait_group %0;\n" :: "n"(S - 2));
    __syncthreads();

    for (int kt = 0; kt < nt; kt++) {
        int nk = kt + S - 1;
        if (nk < nt) issue(nk % S, nk * 64);
        else asm volatile("cp.async.commit_group;\n");
        compute(kt % S);
        asm volatile("cp.async.wait_group %0;\n" :: "n"(S - 2));
        __syncthreads();
    }

    // ---------------- epilogue ----------------
    #pragma unroll
    for (int i = 0; i < MI; i++)
        #pragma unroll
        for (int j = 0; j < JN; j++) {
            int r  = row0 + wm + i * 16 + gid;
            int cn = col0 + wn + j * 8 + q * 2;
            if (HALF_OUT) {
                *reinterpret_cast<__half2*>(Ch + (size_t)r * ldc + cn) =
                    __floats2half2_rn(cr[i][j][0], cr[i][j][1]);
                *reinterpret_cast<__half2*>(Ch + (size_t)(r + 8) * ldc + cn) =
                    __floats2half2_rn(cr[i][j][2], cr[i][j][3]);
                if (WRITE_Y) {
                    float g0 = __ldg(&g_gate[cn]), g1 = __ldg(&g_gate[cn + 1]);
                    *reinterpret_cast<__half2*>(Yh + (size_t)r * ldc + cn) =
                        __floats2half2_rn(cr[i][j][0] * g0, cr[i][j][1] * g1);
                    *reinterpret_cast<__half2*>(Yh + (size_t)(r + 8) * ldc + cn) =
                        __floats2half2_rn(cr[i][j][2] * g0, cr[i][j][3] * g1);
                }
            } else {
                *reinterpret_cast<float2*>(Cf + (size_t)r * ldc + cn) =
                    make_float2(cr[i][j][0], cr[i][j][1]);
                *reinterpret_cast<float2*>(Cf + (size_t)(r + 8) * ldc + cn) =
                    make_float2(cr[i][j][2], cr[i][j][3]);
            }
        }
}

// ---------------- rmsnorm + residual ----------------------------------------
__global__ __launch_bounds__(256) void rms_kernel(const float* __restrict__ x,
                                                  const float* __restrict__ w,
                                                  float* __restrict__ out)
{
    const int row = blockIdx.x;
    const float* o = g_o + (size_t)row * D_;
    float s = 0.f;
    for (int d = threadIdx.x; d < D_; d += 256) {
        float v = o[d];
        s = fmaf(v, v, s);
    }
    __shared__ float red[8];
    #pragma unroll
    for (int off = 16; off; off >>= 1) s += __shfl_xor_sync(0xFFFFFFFFu, s, off);
    if ((threadIdx.x & 31) == 0) red[threadIdx.x >> 5] = s;
    __syncthreads();
    if (threadIdx.x < 8) {
        float t = red[threadIdx.x];
        #pragma unroll
        for (int off = 4; off; off >>= 1) t += __shfl_xor_sync(0xFFu, t, off);
        if (threadIdx.x == 0) red[0] = t;
    }
    __syncthreads();
    const float scale = rsqrtf(red[0] * (1.0f / D_) + 1.1920928955078125e-7f);
    for (int d = threadIdx.x; d < D_; d += 256) {
        out[(size_t)row * D_ + d] =
            x[(size_t)row * D_ + d] + o[d] * scale * w[d];
    }
}

// ---------------- launch -----------------------------------------------------
extern "C" void kernel_launch(void* const* d_in, const int* in_sizes, int n_in,
                              void* d_out, int out_size)
{
    const float* x     = (const float*)d_in[0];
    const float* W_in  = (const float*)d_in[1];
    const float* W_out = (const float*)d_in[2];
    // d_in[3] = A_theta: dead (initial state is zero)
    const float* Br    = (const float*)d_in[4];
    const float* Bi    = (const float*)d_in[5];
    const float* Cr    = (const float*)d_in[6];
    const float* Ci    = (const float*)d_in[7];
    const float* nw    = (const float*)d_in[8];

    float* out0 = (float*)d_out;
    const long long FULL =
        (long long)BL_ * D_ + 2LL * BL_ * N1_ * DS_;   // 136,314,880
    const int write_state = ((long long)out_size >= FULL) ? 1 : 0;
    float* nr = out0 + (size_t)BL_ * D_;
    float* ni = nr + (size_t)BL_ * N1_ * DS_;

    void *w1_p = nullptr, *w2_p = nullptr, *xh_p = nullptr, *xih_p = nullptr,
         *yh_p = nullptr, *o_p = nullptr;
    cudaGetSymbolAddress(&w1_p,  g_Wh1);
    cudaGetSymbolAddress(&w2_p,  g_Wh2);
    cudaGetSymbolAddress(&xh_p,  g_xh);
    cudaGetSymbolAddress(&xih_p, g_xih);
    cudaGetSymbolAddress(&yh_p,  g_yh);
    cudaGetSymbolAddress(&o_p,   g_o);

    const int SMEM = 3 * (128 + 128) * 72 * 2;   // 110,592 B
    cudaFuncSetAttribute((const void*)gemm_tn<true,  true >,
                         cudaFuncAttributeMaxDynamicSharedMemorySize, SMEM);
    cudaFuncSetAttribute((const void*)gemm_tn<false, false>,
                         cudaFuncAttributeMaxDynamicSharedMemorySize, SMEM);

    static cudaStream_t side = nullptr;
    static cudaEvent_t evF = nullptr, evW2 = nullptr, evXI = nullptr, evST = nullptr;
    if (!side) {
        if (cudaStreamCreateWithFlags(&side, cudaStreamNonBlocking) != cudaSuccess)
            side = nullptr;
        if (side) {
            cudaEventCreateWithFlags(&evF,  cudaEventDisableTiming);
            cudaEventCreateWithFlags(&evW2, cudaEventDisableTiming);
            cudaEventCreateWithFlags(&evXI, cudaEventDisableTiming);
            cudaEventCreateWithFlags(&evST, cudaEventDisableTiming);
        }
    }
    const bool fork = (side != nullptr);

    const int na = N1_ * D_ / 4;   // W_in float4 count
    const int nb = D_ * N1_ / 4;   // W_out float4 count
    const int nc = BL_ * D_ / 4;   // x float4 count

    const dim3 G1(N1_ / 128, BL_ / 128);   // 32 x 8 = 256 CTAs
    const dim3 G2(D_  / 128, BL_ / 128);   // 16 x 8 = 128 CTAs

    if (fork) {
        cudaEventRecord(evF, 0);
        cudaStreamWaitEvent(side, evF, 0);

        // side: convert W_out (only needed by GEMM2)
        to_half<<<(nb + 255) / 256, 256, 0, side>>>(
            (const float4*)W_out, (__half2*)w2_p, nb);
        cudaEventRecord(evW2, side);

        // main: convert W_in + x, gate, GEMM1 (writes xi AND y)
        to_half2<<<(na + nc + 255) / 256, 256>>>(
            (const float4*)W_in, (__half2*)w1_p, na,
            (const float4*)x,    (__half2*)xh_p, nc);
        compute_gate<<<(4 * N1_) / 256, 256>>>(
            (const float4*)Br, (const float4*)Bi,
            (const float4*)Cr, (const float4*)Ci);
        gemm_tn<true, true><<<G1, 128, SMEM>>>(
            (const __half*)xh_p, (const __half*)w1_p,
            nullptr, (__half*)xih_p, (__half*)yh_p, N1_, D_);

        // side: nr/ni emission
        cudaEventRecord(evXI, 0);
        cudaStreamWaitEvent(side, evXI, 0);
        if (write_state) {
            ew_state<<<512, 256, 0, side>>>(
                (const __half*)xih_p,
                (const float4*)Br, (const float4*)Bi,
                (float4*)nr, (float4*)ni);
        }
        cudaEventRecord(evST, side);

        // main: GEMM2, rms
        cudaStreamWaitEvent(0, evW2, 0);
        gemm_tn<false, false><<<G2, 128, SMEM>>>(
            (const __half*)yh_p, (const __half*)w2_p,
            (float*)o_p, nullptr, nullptr, D_, N1_);
        rms_kernel<<<BL_, 256>>>(x, nw, out0);

        cudaStreamWaitEvent(0, evST, 0);
    } else {
        to_half<<<(nb + 255) / 256, 256>>>((const float4*)W_out, (__half2*)w2_p, nb);
        to_half2<<<(na + nc + 255) / 256, 256>>>(
            (const float4*)W_in, (__half2*)w1_p, na,
            (const float4*)x,    (__half2*)xh_p, nc);
        compute_gate<<<(4 * N1_) / 256, 256>>>(
            (const float4*)Br, (const float4*)Bi,
            (const float4*)Cr, (const float4*)Ci);
        gemm_tn<true, true><<<G1, 128, SMEM>>>(
            (const __half*)xh_p, (const __half*)w1_p,
            nullptr, (__half*)xih_p, (__half*)yh_p, N1_, D_);
        gemm_tn<false, false><<<G2, 128, SMEM>>>(
            (const __half*)yh_p, (const __half*)w2_p,
            (float*)o_p, nullptr, nullptr, D_, N1_);
        if (write_state) {
            ew_state<<<512, 256>>>(
                (const __half*)xih_p,
                (const float4*)Br, (const float4*)Bi,
                (float4*)nr, (float4*)ni);
        }
        rms_kernel<<<BL_, 256>>>(x, nw, out0);
    }
}